// round 5
// baseline (speedup 1.0000x reference)
#include <cuda_runtime.h>
#include <cuda_bf16.h>
#include <cstdint>

// ============================================================================
// GFDreConv: out[b,o,h,w] = sum_{k<2304} W[o,k] * X[k](b,h,w)
//   k<256: X = feat[b,k,h,w];  else s=k/256-1, c=k%256,
//   X = feat[b,c,sy-1,sx-1] (coords are clip()+1 -> always in-bounds).
// feat transposed to [b][sp][c] so gathered K-runs are contiguous.
// GEMM via mma.sync m16n8k16 bf16, 3-term hi/lo split, fp32 accum.
// This round: 2 CTAs/SM + coalesced f_prep (dynamic smem, fixes 48KB limit).
// ============================================================================

#define KTOT 2304
#define BK   32
#define NC   (KTOT / BK)   // 72

__device__ __align__(16) __nv_bfloat16 g_Whi[256 * KTOT];
__device__ __align__(16) __nv_bfloat16 g_Wlo[256 * KTOT];
__device__ __align__(16) __nv_bfloat16 g_Fhi[8ull * 4096 * 256];
__device__ __align__(16) __nv_bfloat16 g_Flo[8ull * 4096 * 256];

// smem rows padded to 40 halves (80B): ldmatrix phase stride 5 (16B units),
// coprime with 8 -> conflict-free.
#define LDS_ROW 40
#define BUF_H   (128 * LDS_ROW)
#define OFF_AH  0
#define OFF_AL  20480
#define OFF_BH  40960
#define OFF_BL  61440
#define OFF_GO  81920
#define SMEM_TOTAL (OFF_GO + 9 * 128 * 4)  // 86528 B -> 2 CTAs/SM fits 228KB

#define FPREP_SMEM (256 * 64 * 4)          // 64KB dynamic

__device__ __forceinline__ uint32_t s2u(const void* p) {
    uint32_t a;
    asm("{ .reg .u64 t; cvta.to.shared.u64 t, %1; cvt.u32.u64 %0, t; }" : "=r"(a) : "l"(p));
    return a;
}
__device__ __forceinline__ void cpa(uint32_t d, const void* g) {
    asm volatile("cp.async.cg.shared.global [%0], [%1], 16;" :: "r"(d), "l"(g));
}

#define LDSM4(r, a)                                                            \
    asm volatile("ldmatrix.sync.aligned.m8n8.x4.shared.b16 {%0,%1,%2,%3},[%4];"\
                 : "=r"((r)[0]), "=r"((r)[1]), "=r"((r)[2]), "=r"((r)[3])      \
                 : "r"(a))
#define LDSM2(r0, r1, a)                                                       \
    asm volatile("ldmatrix.sync.aligned.m8n8.x2.shared.b16 {%0,%1},[%2];"      \
                 : "=r"(r0), "=r"(r1) : "r"(a))
#define MMA(c, a, b0, b1)                                                      \
    asm volatile("mma.sync.aligned.m16n8k16.row.col.f32.bf16.bf16.f32 "        \
                 "{%0,%1,%2,%3},{%4,%5,%6,%7},{%8,%9},{%0,%1,%2,%3};"          \
                 : "+f"((c)[0]), "+f"((c)[1]), "+f"((c)[2]), "+f"((c)[3])      \
                 : "r"((a)[0]), "r"((a)[1]), "r"((a)[2]), "r"((a)[3]),         \
                   "r"(b0), "r"(b1))

// ---------------------------------------------------------------------------
// Prep 1: split W into bf16 hi/lo, row-major [o][k].
// ---------------------------------------------------------------------------
__global__ void w_prep(const float* __restrict__ Wc) {
    int idx = blockIdx.x * 256 + threadIdx.x;
    float v = Wc[idx];
    __nv_bfloat16 hi = __float2bfloat16(v);
    __nv_bfloat16 lo = __float2bfloat16(v - __bfloat162float(hi));
    g_Whi[idx] = hi;
    g_Wlo[idx] = lo;
}

// ---------------------------------------------------------------------------
// Prep 2 (coalesced): transpose feat [b][c][y][x] -> [b][y*64+x][c] hi/lo.
// One block per (b,y). Stage the full 256x64 f32 slice in DYNAMIC smem
// (64KB), then each thread emits contiguous 128B hi + 128B lo runs; 4
// consecutive lanes cover one 512B sp-row -> fully coalesced stores.
// ---------------------------------------------------------------------------
__global__ void __launch_bounds__(256, 1) f_prep(const float* __restrict__ feat) {
    extern __shared__ float tile[];      // [c][x] = 256*64 f32
    const int b = blockIdx.x >> 6;
    const int y = blockIdx.x & 63;
    const int t = threadIdx.x;

    const float* src = feat + (((size_t)b * 256) * 64 + y) * 64;
    for (int idx = t; idx < 256 * 64; idx += 256) {
        int c = idx >> 6, x = idx & 63;
        tile[idx] = src[(size_t)c * 4096 + x];
    }
    __syncthreads();

    const int x = t >> 2;
    const int c0 = (t & 3) * 64;
    const size_t obase = ((size_t)b * 4096 + (size_t)y * 64 + x) * 256 + c0;
    uint4* dh = (uint4*)(g_Fhi + obase);
    uint4* dl = (uint4*)(g_Flo + obase);
#pragma unroll
    for (int j = 0; j < 8; j++) {
        __nv_bfloat16 hbuf[8], lbuf[8];
#pragma unroll
        for (int i = 0; i < 8; i++) {
            float v = tile[(c0 + j * 8 + i) * 64 + x];
            __nv_bfloat16 hi = __float2bfloat16(v);
            hbuf[i] = hi;
            lbuf[i] = __float2bfloat16(v - __bfloat162float(hi));
        }
        dh[j] = *(const uint4*)hbuf;
        dl[j] = *(const uint4*)lbuf;
    }
}

// ---------------------------------------------------------------------------
// Main: 512 CTAs (2 M-blocks x 256 N-blocks), 256 threads (8 warps, 4Mx2N),
// 2 CTAs/SM.
// ---------------------------------------------------------------------------
__global__ void __launch_bounds__(256, 2)
gfd_mma(const int* __restrict__ sx, const int* __restrict__ sy,
        float* __restrict__ out) {
    extern __shared__ char sm[];
    const uint32_t sb = s2u(sm);

    const int t = threadIdx.x, lane = t & 31, wid = t >> 5;
    const int wm = wid & 3, wn = wid >> 2;
    const int mblk = blockIdx.x & 1, nblk = blockIdx.x >> 1;
    const int b = nblk >> 5;
    const int sp0 = (nblk & 31) * 128;

    int* gofs = (int*)(sm + OFF_GO);
    for (int i = t; i < 9 * 128; i += 256) {
        int s = i >> 7, nn = i & 127;
        int sp = sp0 + nn;
        int v;
        if (s == 0) v = sp;
        else {
            int idx = sp * 8 + (s - 1);
            v = (sy[idx] - 1) * 64 + (sx[idx] - 1);
        }
        gofs[i] = v;
    }
    __syncthreads();

    const int arow = t >> 2;
    const int ach = t & 3;
    const size_t fb = (size_t)b * 4096 * 256;
    const __nv_bfloat16* wHbase = g_Whi + (size_t)(mblk * 128) * KTOT;
    const __nv_bfloat16* wLbase = g_Wlo + (size_t)(mblk * 128) * KTOT;

    float acc[2][8][4];
#pragma unroll
    for (int i = 0; i < 2; i++)
#pragma unroll
        for (int j = 0; j < 8; j++)
#pragma unroll
            for (int q = 0; q < 4; q++) acc[i][j][q] = 0.0f;

    auto issue = [&](int kc, int buf) {
        const int k0 = kc * BK;
        const int s = kc >> 3;
        const int c0 = (kc & 7) * 32;
        const uint32_t bufh = (uint32_t)buf * BUF_H;
#pragma unroll
        for (int j = 0; j < 2; j++) {
            const int row = arow + j * 64;
            const uint32_t doff = (bufh + (uint32_t)row * LDS_ROW + ach * 8) * 2;
            cpa(sb + OFF_AH + doff, wHbase + (size_t)row * KTOT + k0 + ach * 8);
            cpa(sb + OFF_AL + doff, wLbase + (size_t)row * KTOT + k0 + ach * 8);
            const int sp = gofs[s * 128 + row];
            const size_t fo = fb + (size_t)sp * 256 + c0 + ach * 8;
            cpa(sb + OFF_BH + doff, g_Fhi + fo);
            cpa(sb + OFF_BL + doff, g_Flo + fo);
        }
        asm volatile("cp.async.commit_group;" ::: "memory");
    };

    issue(0, 0);
    int buf = 0;

    for (int kc = 0; kc < NC; kc++) {
        if (kc + 1 < NC) {
            issue(kc + 1, buf ^ 1);
            asm volatile("cp.async.wait_group 1;" ::: "memory");
        } else {
            asm volatile("cp.async.wait_group 0;" ::: "memory");
        }
        __syncthreads();

        const uint32_t aH = sb + OFF_AH + (uint32_t)buf * BUF_H * 2;
        const uint32_t aL = sb + OFF_AL + (uint32_t)buf * BUF_H * 2;
        const uint32_t bH = sb + OFF_BH + (uint32_t)buf * BUF_H * 2;
        const uint32_t bL = sb + OFF_BL + (uint32_t)buf * BUF_H * 2;

#pragma unroll
        for (int kk = 0; kk < 2; kk++) {
            uint32_t ah[2][4], al[2][4];
#pragma unroll
            for (int i = 0; i < 2; i++) {
                const int row = wm * 32 + i * 16 + (lane & 15);
                const uint32_t off =
                    ((uint32_t)row * LDS_ROW + kk * 16 + (lane >> 4) * 8) * 2;
                LDSM4(ah[i], aH + off);
                LDSM4(al[i], aL + off);
            }
#pragma unroll
            for (int j = 0; j < 8; j++) {
                const int rowb = wn * 64 + j * 8 + (lane & 7);
                const uint32_t off =
                    ((uint32_t)rowb * LDS_ROW + kk * 16 + ((lane >> 3) & 1) * 8) * 2;
                uint32_t bh0, bh1, bl0, bl1;
                LDSM2(bh0, bh1, bH + off);
                LDSM2(bl0, bl1, bL + off);
#pragma unroll
                for (int i = 0; i < 2; i++) {
                    MMA(acc[i][j], ah[i], bh0, bh1);
                    MMA(acc[i][j], ah[i], bl0, bl1);
                    MMA(acc[i][j], al[i], bh0, bh1);
                }
            }
        }
        __syncthreads();
        buf ^= 1;
    }

    const int g = lane >> 2, tig = lane & 3;
#pragma unroll
    for (int i = 0; i < 2; i++) {
        const int o = mblk * 128 + wm * 32 + i * 16 + g;
        float* obase = out + ((size_t)b * 256 + o) * 4096;
#pragma unroll
        for (int j = 0; j < 8; j++) {
            const int sp = sp0 + wn * 64 + j * 8 + tig * 2;
            *(float2*)(obase + sp) = make_float2(acc[i][j][0], acc[i][j][1]);
            *(float2*)(obase + 8 * 4096 + sp) = make_float2(acc[i][j][2], acc[i][j][3]);
        }
    }
}

// ============================================================================
extern "C" void kernel_launch(void* const* d_in, const int* in_sizes, int n_in,
                              void* d_out, int out_size) {
    const float* feat = (const float*)d_in[0];  // (8,256,64,64) f32
    const float* Wc   = (const float*)d_in[1];  // (256,2304) f32
    const int*   sx   = (const int*)d_in[2];    // (64,64,8) i32
    const int*   sy   = (const int*)d_in[3];    // (64,64,8) i32
    float*       out  = (float*)d_out;          // (8,256,64,64) f32

    static bool attr_set = false;
    if (!attr_set) {
        cudaFuncSetAttribute(gfd_mma, cudaFuncAttributeMaxDynamicSharedMemorySize,
                             SMEM_TOTAL);
        cudaFuncSetAttribute(f_prep, cudaFuncAttributeMaxDynamicSharedMemorySize,
                             FPREP_SMEM);
        attr_set = true;
    }

    w_prep<<<2304, 256>>>(Wc);
    f_prep<<<512, 256, FPREP_SMEM>>>(feat);
    gfd_mma<<<512, 256, SMEM_TOTAL>>>(sx, sy, out);
}

// round 6
// speedup vs baseline: 1.8636x; 1.8636x over previous
#include <cuda_runtime.h>
#include <cuda_fp16.h>
#include <cstdint>

// ============================================================================
// GFDreConv: out[b,o,h,w] = sum_{k<2304} W[o,k] * X[k](b,h,w)
//   k<256: X = feat[b,k,h,w]; else s=k/256-1, c=k%256,
//   X = feat[b,c,sy-1,sx-1] (coords are clip()+1 -> always in-bounds).
// feat transposed to [b][sp][c] fp16 so gathered K-runs are contiguous.
// SINGLE-PASS fp16 mma.sync m16n8k16 (fp32 accum): rel_err ~3e-4 (RMS of two
// 2^-11 roundings), threshold 1e-3. 3x fewer MMAs than the 3-term bf16 split.
// ============================================================================

#define KTOT 2304
#define BK   64
#define NC   (KTOT / BK)   // 36

__device__ __align__(16) __half g_Wh[256 * KTOT];            // 1.15 MB
__device__ __align__(16) __half g_Fh[8ull * 4096 * 256];     // 16 MB (L2-resident)

// smem rows: 64 halves + 8 pad = 72 halves (144B) -> ldmatrix phase stride 9,
// coprime with 8 banks => conflict-free.
#define LDS_ROW 72
#define BUF_H   (128 * LDS_ROW)            // 9216 halves = 18432 B per buffer
#define OFF_A   0                          // 2 buffers: 36864 B
#define OFF_B   36864                      // 2 buffers: 36864 B
#define OFF_GO  73728                      // 9*128 ints = 4608 B
#define SMEM_TOTAL (OFF_GO + 9 * 128 * 4)  // 78336 B -> 2 CTAs/SM

#define FPREP_SMEM (256 * 64 * 4)          // 64 KB dynamic

__device__ __forceinline__ uint32_t s2u(const void* p) {
    uint32_t a;
    asm("{ .reg .u64 t; cvta.to.shared.u64 t, %1; cvt.u32.u64 %0, t; }" : "=r"(a) : "l"(p));
    return a;
}
__device__ __forceinline__ void cpa(uint32_t d, const void* g) {
    asm volatile("cp.async.cg.shared.global [%0], [%1], 16;" :: "r"(d), "l"(g));
}

#define LDSM4(r, a)                                                            \
    asm volatile("ldmatrix.sync.aligned.m8n8.x4.shared.b16 {%0,%1,%2,%3},[%4];"\
                 : "=r"((r)[0]), "=r"((r)[1]), "=r"((r)[2]), "=r"((r)[3])      \
                 : "r"(a))
#define LDSM2(r0, r1, a)                                                       \
    asm volatile("ldmatrix.sync.aligned.m8n8.x2.shared.b16 {%0,%1},[%2];"      \
                 : "=r"(r0), "=r"(r1) : "r"(a))
#define MMA(c, a, b0, b1)                                                      \
    asm volatile("mma.sync.aligned.m16n8k16.row.col.f32.f16.f16.f32 "          \
                 "{%0,%1,%2,%3},{%4,%5,%6,%7},{%8,%9},{%0,%1,%2,%3};"          \
                 : "+f"((c)[0]), "+f"((c)[1]), "+f"((c)[2]), "+f"((c)[3])      \
                 : "r"((a)[0]), "r"((a)[1]), "r"((a)[2]), "r"((a)[3]),         \
                   "r"(b0), "r"(b1))

// ---------------------------------------------------------------------------
// Prep 1: W -> fp16, row-major [o][k].
// ---------------------------------------------------------------------------
__global__ void w_prep(const float* __restrict__ Wc) {
    int idx = blockIdx.x * 256 + threadIdx.x;
    g_Wh[idx] = __float2half(Wc[idx]);
}

// ---------------------------------------------------------------------------
// Prep 2: transpose feat [b][c][y][x] -> [b][y*64+x][c] fp16, coalesced.
// One block per (b,y): stage 256x64 f32 slice in dynamic smem, emit
// contiguous 128B runs (2 lanes = one 512B sp-row -> fully coalesced).
// ---------------------------------------------------------------------------
__global__ void __launch_bounds__(256, 1) f_prep(const float* __restrict__ feat) {
    extern __shared__ float tile[];      // [c][x] 256*64
    const int b = blockIdx.x >> 6;
    const int y = blockIdx.x & 63;
    const int t = threadIdx.x;

    const float* src = feat + (((size_t)b * 256) * 64 + y) * 64;
    for (int idx = t; idx < 256 * 64; idx += 256) {
        int c = idx >> 6, x = idx & 63;
        tile[idx] = src[(size_t)c * 4096 + x];
    }
    __syncthreads();

    const int x = t >> 2;                 // 0..63
    const int c0 = (t & 3) * 64;
    const size_t obase = ((size_t)b * 4096 + (size_t)y * 64 + x) * 256 + c0;
    uint4* dh = (uint4*)(g_Fh + obase);
#pragma unroll
    for (int j = 0; j < 8; j++) {
        __half hbuf[8];
#pragma unroll
        for (int i = 0; i < 8; i++)
            hbuf[i] = __float2half(tile[(c0 + j * 8 + i) * 64 + x]);
        dh[j] = *(const uint4*)hbuf;
    }
}

// ---------------------------------------------------------------------------
// Main: 512 CTAs (2 M-blocks x 256 N-blocks), 256 threads (8 warps 4Mx2N),
// 2 CTAs/SM (regs ~100, no spill with single-term frags).
// ---------------------------------------------------------------------------
__global__ void __launch_bounds__(256, 2)
gfd_mma(const int* __restrict__ sx, const int* __restrict__ sy,
        float* __restrict__ out) {
    extern __shared__ char sm[];
    const uint32_t sb = s2u(sm);

    const int t = threadIdx.x, lane = t & 31, wid = t >> 5;
    const int wm = wid & 3, wn = wid >> 2;
    const int mblk = blockIdx.x & 1, nblk = blockIdx.x >> 1;
    const int b = nblk >> 5;
    const int sp0 = (nblk & 31) * 128;

    int* gofs = (int*)(sm + OFF_GO);
    for (int i = t; i < 9 * 128; i += 256) {
        int s = i >> 7, nn = i & 127;
        int sp = sp0 + nn;
        int v;
        if (s == 0) v = sp;
        else {
            int idx = sp * 8 + (s - 1);
            v = (sy[idx] - 1) * 64 + (sx[idx] - 1);
        }
        gofs[i] = v;
    }
    __syncthreads();

    const int arow = t >> 1;              // 0..127
    const int hsel = (t & 1) * 32;        // half-row select (halves)
    const size_t fb = (size_t)b * 4096 * 256;
    const __half* wbase = g_Wh + (size_t)(mblk * 128) * KTOT;

    float acc[2][8][4];
#pragma unroll
    for (int i = 0; i < 2; i++)
#pragma unroll
        for (int j = 0; j < 8; j++)
#pragma unroll
            for (int q = 0; q < 4; q++) acc[i][j][q] = 0.0f;

    auto issue = [&](int kc, int buf) {
        const int k0 = kc * BK;
        const int s = kc >> 2;
        const int c0 = (kc & 3) * 64;
        const uint32_t dbase = ((uint32_t)buf * BUF_H + (uint32_t)arow * LDS_ROW + hsel) * 2;
        const __half* ga = wbase + (size_t)arow * KTOT + k0 + hsel;
#pragma unroll
        for (int q = 0; q < 4; q++)
            cpa(sb + OFF_A + dbase + q * 16, ga + q * 8);
        const int sp = gofs[s * 128 + arow];
        const __half* gb = g_Fh + fb + (size_t)sp * 256 + c0 + hsel;
#pragma unroll
        for (int q = 0; q < 4; q++)
            cpa(sb + OFF_B + dbase + q * 16, gb + q * 8);
        asm volatile("cp.async.commit_group;" ::: "memory");
    };

    issue(0, 0);
    int buf = 0;

    for (int kc = 0; kc < NC; kc++) {
        if (kc + 1 < NC) {
            issue(kc + 1, buf ^ 1);
            asm volatile("cp.async.wait_group 1;" ::: "memory");
        } else {
            asm volatile("cp.async.wait_group 0;" ::: "memory");
        }
        __syncthreads();

        const uint32_t aP = sb + OFF_A + (uint32_t)buf * BUF_H * 2;
        const uint32_t bP = sb + OFF_B + (uint32_t)buf * BUF_H * 2;

#pragma unroll
        for (int kk = 0; kk < 4; kk++) {          // four k16 steps of BK=64
            uint32_t ah[2][4];
#pragma unroll
            for (int i = 0; i < 2; i++) {
                const int row = wm * 32 + i * 16 + (lane & 15);
                const uint32_t off =
                    ((uint32_t)row * LDS_ROW + kk * 16 + (lane >> 4) * 8) * 2;
                LDSM4(ah[i], aP + off);
            }
#pragma unroll
            for (int j = 0; j < 8; j++) {
                const int rowb = wn * 64 + j * 8 + (lane & 7);
                const uint32_t off =
                    ((uint32_t)rowb * LDS_ROW + kk * 16 + ((lane >> 3) & 1) * 8) * 2;
                uint32_t b0, b1;
                LDSM2(b0, b1, bP + off);
                MMA(acc[0][j], ah[0], b0, b1);
                MMA(acc[1][j], ah[1], b0, b1);
            }
        }
        __syncthreads();
        buf ^= 1;
    }

    const int g = lane >> 2, tig = lane & 3;
#pragma unroll
    for (int i = 0; i < 2; i++) {
        const int o = mblk * 128 + wm * 32 + i * 16 + g;
        float* obase = out + ((size_t)b * 256 + o) * 4096;
#pragma unroll
        for (int j = 0; j < 8; j++) {
            const int sp = sp0 + wn * 64 + j * 8 + tig * 2;
            *(float2*)(obase + sp) = make_float2(acc[i][j][0], acc[i][j][1]);
            *(float2*)(obase + 8 * 4096 + sp) = make_float2(acc[i][j][2], acc[i][j][3]);
        }
    }
}

// ============================================================================
extern "C" void kernel_launch(void* const* d_in, const int* in_sizes, int n_in,
                              void* d_out, int out_size) {
    const float* feat = (const float*)d_in[0];  // (8,256,64,64) f32
    const float* Wc   = (const float*)d_in[1];  // (256,2304) f32
    const int*   sx   = (const int*)d_in[2];    // (64,64,8) i32
    const int*   sy   = (const int*)d_in[3];    // (64,64,8) i32
    float*       out  = (float*)d_out;          // (8,256,64,64) f32

    static bool attr_set = false;
    if (!attr_set) {
        cudaFuncSetAttribute(gfd_mma, cudaFuncAttributeMaxDynamicSharedMemorySize,
                             SMEM_TOTAL);
        cudaFuncSetAttribute(f_prep, cudaFuncAttributeMaxDynamicSharedMemorySize,
                             FPREP_SMEM);
        attr_set = true;
    }

    w_prep<<<2304, 256>>>(Wc);
    f_prep<<<512, 256, FPREP_SMEM>>>(feat);
    gfd_mma<<<512, 256, SMEM_TOTAL>>>(sx, sy, out);
}

// round 7
// speedup vs baseline: 1.9721x; 1.0582x over previous
#include <cuda_runtime.h>
#include <cuda_fp16.h>
#include <cstdint>

// ============================================================================
// GFDreConv: out[b,o,h,w] = sum_{k<2304} W[o,k] * X[k](b,h,w)
// Single-pass fp16 mma.sync m16n8k16, fp32 accum (rel_err ~3e-4 < 1e-3).
// feat transposed to [b][sp][c] fp16 so gathered K-runs are contiguous.
// This round: 3-stage cp.async pipeline w/ 1 sync per chunk, ldmatrix.x4 for
// B, fused prep kernel.
// ============================================================================

#define KTOT 2304
#define BK   64
#define NC   (KTOT / BK)   // 36

__device__ __align__(16) __half g_Wh[256 * KTOT];
__device__ __align__(16) __half g_Fh[8ull * 4096 * 256];     // 16 MB, L2-resident

// smem rows: 64 halves + 8 pad = 72 halves (144B): ldmatrix phase stride 9,
// coprime with 8 banks -> conflict-free.
#define LDS_ROW 72
#define STAGE_H (128 * LDS_ROW)            // halves per (A or B) stage: 9216
#define STAGE_B (STAGE_H * 2)              // 18432 B
#define OFF_A   0                          // 3 stages A: 55296 B
#define OFF_B   (3 * STAGE_B)              // 3 stages B: 55296 B
#define OFF_GO  (6 * STAGE_B)              // 9*128 u16 = 2304 B
#define SMEM_TOTAL (OFF_GO + 9 * 128 * 2)  // 112896 B -> 2 CTAs/SM (225.8KB)

#define FPREP_SMEM (256 * 64 * 4)          // 64 KB dynamic

__device__ __forceinline__ uint32_t s2u(const void* p) {
    uint32_t a;
    asm("{ .reg .u64 t; cvta.to.shared.u64 t, %1; cvt.u32.u64 %0, t; }" : "=r"(a) : "l"(p));
    return a;
}
__device__ __forceinline__ void cpa(uint32_t d, const void* g) {
    asm volatile("cp.async.cg.shared.global [%0], [%1], 16;" :: "r"(d), "l"(g));
}

#define LDSM4(r, a)                                                            \
    asm volatile("ldmatrix.sync.aligned.m8n8.x4.shared.b16 {%0,%1,%2,%3},[%4];"\
                 : "=r"((r)[0]), "=r"((r)[1]), "=r"((r)[2]), "=r"((r)[3])      \
                 : "r"(a))
#define MMA(c, a, b0, b1)                                                      \
    asm volatile("mma.sync.aligned.m16n8k16.row.col.f32.f16.f16.f32 "          \
                 "{%0,%1,%2,%3},{%4,%5,%6,%7},{%8,%9},{%0,%1,%2,%3};"          \
                 : "+f"((c)[0]), "+f"((c)[1]), "+f"((c)[2]), "+f"((c)[3])      \
                 : "r"((a)[0]), "r"((a)[1]), "r"((a)[2]), "r"((a)[3]),         \
                   "r"(b0), "r"(b1))

// ---------------------------------------------------------------------------
// Fused prep. Blocks [0,512): transpose feat (b,y slice) -> [b][sp][c] fp16.
// Blocks [512,800): W -> fp16 (2048 elems/block, vectorized).
// ---------------------------------------------------------------------------
__global__ void __launch_bounds__(256, 1)
prep(const float* __restrict__ feat, const float* __restrict__ Wc) {
    const int t = threadIdx.x;
    if (blockIdx.x >= 512) {
        const int base = (blockIdx.x - 512) * 2048 + t * 8;
        float4 v0 = *(const float4*)(Wc + base);
        float4 v1 = *(const float4*)(Wc + base + 4);
        __half hb[8];
        hb[0] = __float2half(v0.x); hb[1] = __float2half(v0.y);
        hb[2] = __float2half(v0.z); hb[3] = __float2half(v0.w);
        hb[4] = __float2half(v1.x); hb[5] = __float2half(v1.y);
        hb[6] = __float2half(v1.z); hb[7] = __float2half(v1.w);
        *(uint4*)(g_Wh + base) = *(const uint4*)hb;
        return;
    }
    extern __shared__ float tile[];      // [c][x] 256*64 f32
    const int b = blockIdx.x >> 6;
    const int y = blockIdx.x & 63;
    const float* src = feat + (((size_t)b * 256) * 64 + y) * 64;
    for (int idx = t; idx < 256 * 64; idx += 256) {
        int c = idx >> 6, x = idx & 63;
        tile[idx] = src[(size_t)c * 4096 + x];
    }
    __syncthreads();
    const int x = t >> 2;
    const int c0 = (t & 3) * 64;
    uint4* dh = (uint4*)(g_Fh + ((size_t)b * 4096 + (size_t)y * 64 + x) * 256 + c0);
#pragma unroll
    for (int j = 0; j < 8; j++) {
        __half hbuf[8];
#pragma unroll
        for (int i = 0; i < 8; i++)
            hbuf[i] = __float2half(tile[(c0 + j * 8 + i) * 64 + x]);
        dh[j] = *(const uint4*)hbuf;
    }
}

// ---------------------------------------------------------------------------
// Main: 512 CTAs (2 M x 256 N-blocks), 256 threads (8 warps 4Mx2N), 2 CTA/SM.
// 3-stage cp.async pipeline, single __syncthreads per chunk.
// ---------------------------------------------------------------------------
__global__ void __launch_bounds__(256, 2)
gfd_mma(const int* __restrict__ sx, const int* __restrict__ sy,
        float* __restrict__ out) {
    extern __shared__ char sm[];
    const uint32_t sb = s2u(sm);

    const int t = threadIdx.x, lane = t & 31, wid = t >> 5;
    const int wm = wid & 3, wn = wid >> 2;
    const int mblk = blockIdx.x & 1, nblk = blockIdx.x >> 1;
    const int b = nblk >> 5;
    const int sp0 = (nblk & 31) * 128;

    uint16_t* gofs = (uint16_t*)(sm + OFF_GO);
    for (int i = t; i < 9 * 128; i += 256) {
        int s = i >> 7, nn = i & 127;
        int sp = sp0 + nn;
        int v;
        if (s == 0) v = sp;
        else {
            int idx = sp * 8 + (s - 1);
            v = (sy[idx] - 1) * 64 + (sx[idx] - 1);
        }
        gofs[i] = (uint16_t)v;
    }
    __syncthreads();

    const int arow = t >> 1;              // 0..127
    const int hsel = (t & 1) * 32;        // half-row (in halves)
    const size_t fb = (size_t)b * 4096 * 256;
    const __half* wbase = g_Wh + (size_t)(mblk * 128) * KTOT;

    float acc[2][8][4];
#pragma unroll
    for (int i = 0; i < 2; i++)
#pragma unroll
        for (int j = 0; j < 8; j++)
#pragma unroll
            for (int q = 0; q < 4; q++) acc[i][j][q] = 0.0f;

    auto issue = [&](int kc) {
        const int stg = kc % 3;
        const int k0 = kc * BK;
        const int s = kc >> 2;
        const int c0 = (kc & 3) * 64;
        const uint32_t dbase =
            ((uint32_t)stg * STAGE_H + (uint32_t)arow * LDS_ROW + hsel) * 2;
        const __half* ga = wbase + (size_t)arow * KTOT + k0 + hsel;
#pragma unroll
        for (int q = 0; q < 4; q++)
            cpa(sb + OFF_A + dbase + q * 16, ga + q * 8);
        const int sp = gofs[s * 128 + arow];
        const __half* gb = g_Fh + fb + (size_t)sp * 256 + c0 + hsel;
#pragma unroll
        for (int q = 0; q < 4; q++)
            cpa(sb + OFF_B + dbase + q * 16, gb + q * 8);
        asm volatile("cp.async.commit_group;" ::: "memory");
    };

    issue(0);
    issue(1);

    for (int kc = 0; kc < NC; kc++) {
        if (kc == NC - 1) {
            asm volatile("cp.async.wait_group 0;" ::: "memory");
        } else {
            asm volatile("cp.async.wait_group 1;" ::: "memory");
        }
        __syncthreads();
        if (kc + 2 < NC) issue(kc + 2);

        const int stg = kc % 3;
        const uint32_t aP = sb + OFF_A + (uint32_t)stg * STAGE_B;
        const uint32_t bP = sb + OFF_B + (uint32_t)stg * STAGE_B;

#pragma unroll
        for (int kk = 0; kk < 4; kk++) {
            uint32_t ah[2][4];
#pragma unroll
            for (int i = 0; i < 2; i++) {
                const int row = wm * 32 + i * 16 + (lane & 15);
                const uint32_t off =
                    ((uint32_t)row * LDS_ROW + kk * 16 + (lane >> 4) * 8) * 2;
                LDSM4(ah[i], aP + off);
            }
#pragma unroll
            for (int j2 = 0; j2 < 4; j2++) {
                // x4: m0,m1 = rows j2*16+0..7 (k lo/hi); m2,m3 = rows +8..15
                const int rowb = wn * 64 + j2 * 16 + (lane >> 4) * 8 + (lane & 7);
                const uint32_t off =
                    ((uint32_t)rowb * LDS_ROW + kk * 16 + ((lane >> 3) & 1) * 8) * 2;
                uint32_t bf[4];
                LDSM4(bf, bP + off);
                MMA(acc[0][j2 * 2],     ah[0], bf[0], bf[1]);
                MMA(acc[1][j2 * 2],     ah[1], bf[0], bf[1]);
                MMA(acc[0][j2 * 2 + 1], ah[0], bf[2], bf[3]);
                MMA(acc[1][j2 * 2 + 1], ah[1], bf[2], bf[3]);
            }
        }
    }

    const int g = lane >> 2, tig = lane & 3;
#pragma unroll
    for (int i = 0; i < 2; i++) {
        const int o = mblk * 128 + wm * 32 + i * 16 + g;
        float* obase = out + ((size_t)b * 256 + o) * 4096;
#pragma unroll
        for (int j = 0; j < 8; j++) {
            const int sp = sp0 + wn * 64 + j * 8 + tig * 2;
            *(float2*)(obase + sp) = make_float2(acc[i][j][0], acc[i][j][1]);
            *(float2*)(obase + 8 * 4096 + sp) = make_float2(acc[i][j][2], acc[i][j][3]);
        }
    }
}

// ============================================================================
extern "C" void kernel_launch(void* const* d_in, const int* in_sizes, int n_in,
                              void* d_out, int out_size) {
    const float* feat = (const float*)d_in[0];  // (8,256,64,64) f32
    const float* Wc   = (const float*)d_in[1];  // (256,2304) f32
    const int*   sx   = (const int*)d_in[2];    // (64,64,8) i32
    const int*   sy   = (const int*)d_in[3];    // (64,64,8) i32
    float*       out  = (float*)d_out;          // (8,256,64,64) f32

    static bool attr_set = false;
    if (!attr_set) {
        cudaFuncSetAttribute(gfd_mma, cudaFuncAttributeMaxDynamicSharedMemorySize,
                             SMEM_TOTAL);
        cudaFuncSetAttribute(prep, cudaFuncAttributeMaxDynamicSharedMemorySize,
                             FPREP_SMEM);
        attr_set = true;
    }

    prep<<<800, 256, FPREP_SMEM>>>(feat, Wc);
    gfd_mma<<<512, 256, SMEM_TOTAL>>>(sx, sy, out);
}